// round 11
// baseline (speedup 1.0000x reference)
#include <cuda_runtime.h>
#include <cuda_bf16.h>
#include <math.h>

#define NPTS 64
#define NCF  32
#define NB   30
#define NITER 20
#define NPROB (256*512)
#define PI_D 3.14159265358979323846

#define BSS 40   // bf16 per column of B staging (32 + 8 pad)
#define FSS 72   // bf16 per column of F staging (64 + 8 pad)

// ===================== compile-time constant tables (R4-proven) =============
struct Tbl {
    float G[NPTS][NB];   // G[k][m] = T[m+2](tch_k) - P0[m] - P1[m]*tch_k
    float C[NPTS][NB];   // Phi_c^T
    float V[NB];
    float P0[NB], P1[NB];
    float TC1[NPTS];     // 1 + tch[k]
};

constexpr double ccos(double x) {
    double x2 = x * x, term = 1.0, s = 1.0;
    for (int n = 1; n <= 25; n++) { term *= -x2 / ((2.0*n - 1.0) * (2.0*n)); s += term; }
    return s;
}

constexpr Tbl make_tbl() {
    Tbl R{};
    double tch[NPTS] = {}, Dt[NPTS] = {};
    for (int k = 0; k < NPTS; k++) tch[k] = -ccos(PI_D * (double)k / (double)NPTS);
    for (int k = 0; k < NPTS; k++) {
        double tn = (k == NPTS-1) ? 1.0 : tch[k+1];
        Dt[k] = tn - tch[k];
    }
    double T[NCF][NPTS] = {}, DT[NCF][NPTS] = {};
    for (int k = 0; k < NPTS; k++) {
        double t = tch[k];
        T[0][k] = 1.0; T[1][k] = t;
        for (int n = 2; n < NCF; n++) T[n][k] = 2.0*t*T[n-1][k] - T[n-2][k];
        double Ua = 1.0, Ub = 2.0*t;
        DT[0][k] = 0.0; DT[1][k] = 1.0; DT[2][k] = 2.0*Ub;
        for (int n = 3; n < NCF; n++) {
            double Uc = 2.0*t*Ub - Ua;
            DT[n][k] = (double)n * Uc;
            Ua = Ub; Ub = Uc;
        }
    }
    double P0[NB] = {}, P1[NB] = {};
    for (int m = 0; m < NB; m++) { double d0 = DT[m+2][0]; P1[m] = d0; P0[m] = T[m+2][0] + d0; }
    double Gb[NB][NPTS] = {};
    for (int m = 0; m < NB; m++)
        for (int k = 0; k < NPTS; k++) Gb[m][k] = DT[m+2][k] - P1[m];
    double M[NB][2*NB] = {};
    for (int i = 0; i < NB; i++)
        for (int j = 0; j < NB; j++) {
            double s = 0.0;
            for (int k = 0; k < NPTS; k++) s += Gb[i][k]*Dt[k]*Gb[j][k];
            M[i][j] = s;
            M[i][NB+j] = (i == j) ? 1.0 : 0.0;
        }
    for (int col = 0; col < NB; col++) {
        int p = col; double best = M[col][col] < 0 ? -M[col][col] : M[col][col];
        for (int r = col+1; r < NB; r++) {
            double v = M[r][col] < 0 ? -M[r][col] : M[r][col];
            if (v > best) { best = v; p = r; }
        }
        if (p != col)
            for (int c = 0; c < 2*NB; c++) { double tmp = M[col][c]; M[col][c] = M[p][c]; M[p][c] = tmp; }
        double piv = M[col][col];
        for (int c = 0; c < 2*NB; c++) M[col][c] /= piv;
        for (int r = 0; r < NB; r++) if (r != col) {
            double f = M[r][col];
            for (int c = 0; c < 2*NB; c++) M[r][c] -= f * M[col][c];
        }
    }
    double Cd[NPTS][NB] = {};
    for (int k = 0; k < NPTS; k++)
        for (int m = 0; m < NB; m++) {
            double s = 0.0;
            for (int j = 0; j < NB; j++) s += Gb[j][k] * M[j][NB+m];
            Cd[k][m] = Dt[k] * s;
        }
    for (int k = 0; k < NPTS; k++)
        for (int m = 0; m < NB; m++) {
            R.G[k][m] = (float)(T[m+2][k] - P0[m] - P1[m]*tch[k]);
            R.C[k][m] = (float)Cd[k][m];
        }
    for (int m = 0; m < NB; m++) {
        double v = 0.0;
        for (int k = 0; k < NPTS; k++) v += Cd[k][m];
        R.V[m] = (float)v; R.P0[m] = (float)P0[m]; R.P1[m] = (float)P1[m];
    }
    for (int k = 0; k < NPTS; k++) R.TC1[k] = (float)(1.0 + tch[k]);
    return R;
}

__device__ constexpr Tbl d_TB = make_tbl();

// ------------------------ runtime-filled constants --------------------------
// Fragment-order packed A matrices (thread-major: one uint4 per lane per (kt,mt))
__device__ unsigned g_Gfrag[2048];   // [hi(0)/lo(1024)][kt(2)][mt(4)][lane*4+w]
__device__ unsigned g_Cfrag[2048];   // [hi/lo][kt(4)][mt(2)][lane*4+w]
__device__ float c_sin[NPTS];
__device__ float c_V[NCF];           // zero-padded V
__device__ float c_PO[NCF][16];
__device__ float c_scal[2];          // inv_s, sin(t0)

// ==================== setup kernel: tiny (runtime-only parts) ===============
__global__ void setup_kernel(const float* __restrict__ tspan) {
    int tid = threadIdx.x;
    double t0 = (double)tspan[0];
    double t1 = (double)tspan[15];
    double inv_s = 0.5 * (t1 - t0);

    // ---- G fragments (thread-major): e -> (kt, mt, lane, w) ----
    for (int e = tid; e < 1024; e += blockDim.x) {
        int kt = e >> 9, rem = e & 511;
        int mt = rem >> 7, rem2 = rem & 127;
        int lane = rem2 >> 2, w = rem2 & 3;
        int g = lane >> 2, t = lane & 3;
        int row = mt*16 + ((w & 1) ? 8 : 0) + g;
        int cp  = kt*8 + ((w & 2) ? 4 : 0) + t;
        int m0 = 2*cp, m1 = 2*cp + 1;
        float f0 = (m0 < NB) ? d_TB.G[row][m0] : 0.f;
        float f1 = (m1 < NB) ? d_TB.G[row][m1] : 0.f;
        __nv_bfloat16 h0 = __float2bfloat16(f0), h1 = __float2bfloat16(f1);
        __nv_bfloat16 l0 = __float2bfloat16(f0 - __bfloat162float(h0));
        __nv_bfloat16 l1 = __float2bfloat16(f1 - __bfloat162float(h1));
        unsigned short b; unsigned wh, wl;
        memcpy(&b, &h0, 2); wh = b;
        memcpy(&b, &h1, 2); wh |= (unsigned)b << 16;
        memcpy(&b, &l0, 2); wl = b;
        memcpy(&b, &l1, 2); wl |= (unsigned)b << 16;
        g_Gfrag[e]        = wh;
        g_Gfrag[1024 + e] = wl;
    }
    // ---- C^T fragments: e -> (kt, mt, lane, w) ----
    for (int e = tid; e < 1024; e += blockDim.x) {
        int kt = e >> 8;
        int mt = (e >> 7) & 1;
        int lane = (e >> 2) & 31, w = e & 3;
        int g = lane >> 2, t = lane & 3;
        int row = mt*16 + ((w & 1) ? 8 : 0) + g;     // coef m
        int cp  = kt*8 + ((w & 2) ? 4 : 0) + t;      // point pair
        float f0 = 0.f, f1 = 0.f;
        if (row < NB) { f0 = d_TB.C[2*cp][row]; f1 = d_TB.C[2*cp+1][row]; }
        __nv_bfloat16 h0 = __float2bfloat16(f0), h1 = __float2bfloat16(f1);
        __nv_bfloat16 l0 = __float2bfloat16(f0 - __bfloat162float(h0));
        __nv_bfloat16 l1 = __float2bfloat16(f1 - __bfloat162float(h1));
        unsigned short b; unsigned wh, wl;
        memcpy(&b, &h0, 2); wh = b;
        memcpy(&b, &h1, 2); wh |= (unsigned)b << 16;
        memcpy(&b, &l0, 2); wl = b;
        memcpy(&b, &l1, 2); wl |= (unsigned)b << 16;
        g_Cfrag[e]        = wh;
        g_Cfrag[1024 + e] = wl;
    }

    if (tid < NPTS) c_sin[tid] = (float)sin(t0 + inv_s * (double)d_TB.TC1[tid]);
    if (tid < NCF)  c_V[tid] = (tid < NB) ? d_TB.V[tid] : 0.f;
    if (tid == 0) { c_scal[0] = (float)inv_s; c_scal[1] = (float)sin(t0); }
    if (tid >= 64 && tid < 80) {
        int t = tid - 64;
        double tq = -1.0 + 2.0*((double)tspan[t] - t0)/(t1 - t0);
        double Tm2 = 1.0, Tm1 = tq;
        c_PO[0][t] = 1.0f; c_PO[1][t] = (float)tq;
        #pragma unroll 1
        for (int n = 2; n < NCF; n++) {
            double Tn = 2.0*tq*Tm1 - Tm2; c_PO[n][t] = (float)Tn; Tm2 = Tm1; Tm1 = Tn;
        }
    }
}

// ==================== solve kernel helpers ==================================
__device__ __forceinline__ float fast_tanh(float x) {
    float ax = fabsf(x);
    float e  = __expf(-2.0f * ax);
    float t  = __fdividef(1.0f - e, 1.0f + e);
    return copysignf(t, x);
}

__device__ __forceinline__ void mma_bf16(float* d,
    unsigned a0, unsigned a1, unsigned a2, unsigned a3,
    unsigned b0, unsigned b1)
{
    asm("mma.sync.aligned.m16n8k16.row.col.f32.bf16.bf16.f32 "
        "{%0,%1,%2,%3}, {%4,%5,%6,%7}, {%8,%9}, {%0,%1,%2,%3};"
        : "+f"(d[0]), "+f"(d[1]), "+f"(d[2]), "+f"(d[3])
        : "r"(a0), "r"(a1), "r"(a2), "r"(a3), "r"(b0), "r"(b1));
}

// truncation split: hi = f with low 16 bits zeroed, lo = rn(f - hi)
__device__ __forceinline__ void split_st(float f, __nv_bfloat16* ph, __nv_bfloat16* pl) {
    unsigned u = __float_as_uint(f);
    unsigned short hb = (unsigned short)(u >> 16);
    float hf = __uint_as_float(u & 0xFFFF0000u);
    __nv_bfloat16 h; memcpy(&h, &hb, 2);
    *ph = h;
    *pl = __float2bfloat16(f - hf);
}

// ==================== main solve kernel =====================================
// 1 warp = 32 problems. A-hi fragments in registers (loaded once); A-lo in
// block-shared smem. B/F staged per-warp in smem.
__global__ void __launch_bounds__(128, 3) solve_kernel(
    const float* __restrict__ y_init, const float* __restrict__ Bin,
    const float* __restrict__ a, float* __restrict__ out)
{
    __shared__ alignas(16) __nv_bfloat16 sB[4][2][32*BSS];
    __shared__ alignas(16) __nv_bfloat16 sF[4][2][8*FSS];
    __shared__ alignas(16) unsigned sGlo[1024];
    __shared__ alignas(16) unsigned sClo[1024];

    int tid  = threadIdx.x;
    int wid  = tid >> 5;
    int lane = tid & 31;
    int g = lane >> 2, t = lane & 3;

    // copy lo fragment tables to smem
    {
        const uint4* gsrc = (const uint4*)(g_Gfrag + 1024);
        const uint4* csrc = (const uint4*)(g_Cfrag + 1024);
        uint4* gdst = (uint4*)sGlo;
        uint4* cdst = (uint4*)sClo;
        for (int e = tid; e < 256; e += 128) { gdst[e] = gsrc[e]; cdst[e] = csrc[e]; }
    }

    // hi fragments -> registers (loop-invariant)
    uint4 GhR[2][4], ChR[4][2];
    #pragma unroll
    for (int kt = 0; kt < 2; kt++)
        #pragma unroll
        for (int mt = 0; mt < 4; mt++)
            GhR[kt][mt] = __ldg((const uint4*)&g_Gfrag[((kt*4 + mt)*32 + lane)*4]);
    #pragma unroll
    for (int kt = 0; kt < 4; kt++)
        #pragma unroll
        for (int mt = 0; mt < 2; mt++)
            ChR[kt][mt] = __ldg((const uint4*)&g_Cfrag[((kt*2 + mt)*32 + lane)*4]);

    // per-thread row constants (rows g + 8j)
    float sin_r[8], tc1_r[8];
    #pragma unroll
    for (int j = 0; j < 8; j++) {
        sin_r[j] = __ldg(&c_sin[g + 8*j]);
        tc1_r[j] = d_TB.TC1[g + 8*j];
    }
    float V_r[4];
    #pragma unroll
    for (int j = 0; j < 4; j++) V_r[j] = __ldg(&c_V[g + 8*j]);
    float invs = __ldg(&c_scal[0]);
    float sin0 = __ldg(&c_scal[1]);

    // own problem (column = lane)
    int pbase = blockIdx.x * 128 + wid * 32;
    int pcol  = pbase + lane;
    float y0  = y_init[pcol];
    float aj0 = __ldg(&a[pcol & 511]);
    float w0  = (sin0 - fast_tanh(y0 * aj0)) * invs;

    // initial B staging
    {
        const float* bp = Bin + (long)pcol * NB;
        __nv_bfloat16* bh = &sB[wid][0][lane*BSS];
        __nv_bfloat16* bl = &sB[wid][1][lane*BSS];
        #pragma unroll 1
        for (int m = 0; m < NB; m++) split_st(bp[m], &bh[m], &bl[m]);
        __nv_bfloat16 z = __float2bfloat16(0.f);
        bh[30] = z; bh[31] = z; bl[30] = z; bl[31] = z;
    }
    __syncthreads();   // covers lo-table copy too

    #pragma unroll 1
    for (int it = 0; it < NITER; it++) {
        #pragma unroll 1
        for (int nt = 0; nt < 4; nt++) {
            int c0l = nt*8 + 2*t;
            float yn0 = __shfl_sync(0xffffffffu, y0,  c0l);
            float yn1 = __shfl_sync(0xffffffffu, y0,  c0l + 1);
            float wn0 = __shfl_sync(0xffffffffu, w0,  c0l);
            float wn1 = __shfl_sync(0xffffffffu, w0,  c0l + 1);
            float an0 = __shfl_sync(0xffffffffu, aj0, c0l);
            float an1 = __shfl_sync(0xffffffffu, aj0, c0l + 1);

            // ---- GEMM1: Y = G @ B(:, tile nt) ----
            float acc[4][4];
            #pragma unroll
            for (int mt = 0; mt < 4; mt++)
                #pragma unroll
                for (int r = 0; r < 4; r++) acc[mt][r] = 0.f;

            #pragma unroll
            for (int kt = 0; kt < 2; kt++) {
                int boff = (nt*8 + g)*BSS + kt*16 + 2*t;
                unsigned bh0 = *(const unsigned*)&sB[wid][0][boff];
                unsigned bh1 = *(const unsigned*)&sB[wid][0][boff + 8];
                unsigned bl0 = *(const unsigned*)&sB[wid][1][boff];
                unsigned bl1 = *(const unsigned*)&sB[wid][1][boff + 8];
                #pragma unroll
                for (int mt = 0; mt < 4; mt++) {
                    uint4 ah = GhR[kt][mt];
                    uint4 al = *(const uint4*)&sGlo[((kt*4 + mt)*32 + lane)*4];
                    mma_bf16(acc[mt], ah.x, ah.y, ah.z, ah.w, bh0, bh1);
                    mma_bf16(acc[mt], ah.x, ah.y, ah.z, ah.w, bl0, bl1);
                    mma_bf16(acc[mt], al.x, al.y, al.z, al.w, bh0, bh1);
                }
            }

            // ---- elementwise: ya -> f -> split -> F staging ----
            #pragma unroll
            for (int mt = 0; mt < 4; mt++) {
                #pragma unroll
                for (int r = 0; r < 4; r++) {
                    int s = r >> 1, colsel = r & 1;
                    int j = 2*mt + s;
                    float yv = colsel ? yn1 : yn0;
                    float wv = colsel ? wn1 : wn0;
                    float av = colsel ? an1 : an0;
                    float ya = acc[mt][r] + fmaf(wv, tc1_r[j], yv);
                    float f  = sin_r[j] - fast_tanh(ya * av);
                    int cl = 2*t + colsel;
                    int krow = g + 8*j;
                    split_st(f, &sF[wid][0][cl*FSS + krow], &sF[wid][1][cl*FSS + krow]);
                }
            }
            __syncwarp();

            // ---- GEMM2: Bnew = C^T @ F ----
            float acc2[2][4];
            #pragma unroll
            for (int mt = 0; mt < 2; mt++)
                #pragma unroll
                for (int r = 0; r < 4; r++) acc2[mt][r] = 0.f;

            #pragma unroll
            for (int kt = 0; kt < 4; kt++) {
                int foff = g*FSS + kt*16 + 2*t;
                unsigned fh0 = *(const unsigned*)&sF[wid][0][foff];
                unsigned fh1 = *(const unsigned*)&sF[wid][0][foff + 8];
                unsigned fl0 = *(const unsigned*)&sF[wid][1][foff];
                unsigned fl1 = *(const unsigned*)&sF[wid][1][foff + 8];
                #pragma unroll
                for (int mt = 0; mt < 2; mt++) {
                    uint4 ah = ChR[kt][mt];
                    uint4 al = *(const uint4*)&sClo[((kt*2 + mt)*32 + lane)*4];
                    mma_bf16(acc2[mt], ah.x, ah.y, ah.z, ah.w, fh0, fh1);
                    mma_bf16(acc2[mt], ah.x, ah.y, ah.z, ah.w, fl0, fl1);
                    mma_bf16(acc2[mt], al.x, al.y, al.z, al.w, fh0, fh1);
                }
            }
            __syncwarp();

            // ---- B update + staging write ----
            #pragma unroll
            for (int mt = 0; mt < 2; mt++) {
                #pragma unroll
                for (int r = 0; r < 4; r++) {
                    int s = r >> 1, colsel = r & 1;
                    int j2 = 2*mt + s;
                    int m  = g + 8*j2;
                    float wv = colsel ? wn1 : wn0;
                    float Bv = fmaf(invs, acc2[mt][r], -(wv * V_r[j2]));
                    int nabs = nt*8 + 2*t + colsel;
                    split_st(Bv, &sB[wid][0][nabs*BSS + m], &sB[wid][1][nabs*BSS + m]);
                }
            }
            __syncwarp();
        } // nt
    } // it

    // ==================== epilogue (lane = its own column) ==================
    float Bf[NB];
    {
        const __nv_bfloat16* bh = &sB[wid][0][lane*BSS];
        const __nv_bfloat16* bl = &sB[wid][1][lane*BSS];
        #pragma unroll
        for (int m = 0; m < NB; m++)
            Bf[m] = __bfloat162float(bh[m]) + __bfloat162float(bl[m]);
    }

    float h0 = y0 + w0, h1 = w0;
    #pragma unroll
    for (int m = 0; m < NB; m++) {
        h0 = fmaf(-Bf[m], d_TB.P0[m], h0);
        h1 = fmaf(-Bf[m], d_TB.P1[m], h1);
    }

    float* outB = out + 16L*NPROB;
    {
        float* dst = outB + (long)pcol * NCF;
        dst[0] = h0; dst[1] = h1;
        #pragma unroll
        for (int m = 0; m < NB; m++) dst[2+m] = Bf[m];
    }

    #pragma unroll 1
    for (int tt = 0; tt < 16; tt++) {
        float val = fmaf(h0, __ldg(&c_PO[0][tt]), h1 * __ldg(&c_PO[1][tt]));
        #pragma unroll
        for (int m = 0; m < NB; m++)
            val = fmaf(Bf[m], __ldg(&c_PO[m+2][tt]), val);
        out[(long)tt*NPROB + pcol] = val;
    }
}

// ==================== launch ================================================
extern "C" void kernel_launch(void* const* d_in, const int* in_sizes, int n_in,
                              void* d_out, int out_size) {
    const float* y_init = (const float*)d_in[0];
    const float* B_init = (const float*)d_in[1];
    const float* t_span = (const float*)d_in[2];
    const float* a      = (const float*)d_in[3];
    float* out = (float*)d_out;
    setup_kernel<<<1, 256>>>(t_span);
    solve_kernel<<<NPROB/128, 128>>>(y_init, B_init, a, out);
}